// round 1
// baseline (speedup 1.0000x reference)
#include <cuda_runtime.h>
#include <math.h>

#define BB 4
#define NN 40960
#define KK 16
#define HH 16
#define DD 32
#define BN_EPS 1e-5f

// scratch (device globals: no allocation allowed)
__device__ float g_feat_t[BB * NN * HH];   // feature transposed to [b, n, 16]
__device__ float g_agg1[BB * NN * HH];     // f_agg1 [b, n, 16]

__device__ __forceinline__ float lrelu(float y) { return fmaxf(y, 0.2f * y); }

// ---------------------------------------------------------------------------
// Transpose feature [B,16,N,1] -> [B*N,16]
// ---------------------------------------------------------------------------
__global__ void transpose_feat_kernel(const float* __restrict__ feature) {
    __shared__ float tile[HH][64 + 1];
    int b = blockIdx.y;
    int n0 = blockIdx.x * 64;
    int t = threadIdx.x;  // 256 threads
    int i = t & 63, cq = t >> 6;  // cq in 0..3
    #pragma unroll
    for (int cc = cq; cc < HH; cc += 4)
        tile[cc][i] = feature[(b * HH + cc) * NN + n0 + i];
    __syncthreads();
    int c = t & 15, iq = t >> 4;  // iq in 0..15
    #pragma unroll
    for (int ii = iq; ii < 64; ii += 16)
        g_feat_t[(b * NN + n0 + ii) * HH + c] = tile[c][ii];
}

// ---------------------------------------------------------------------------
// Stage 1: geometry + conv1(+BN,LReLU) + gather(feat) + att_pool_1 -> g_agg1
// One warp per point; 4 warps/CTA; CTA covers 32 consecutive points (8 iters).
// ---------------------------------------------------------------------------
__global__ void __launch_bounds__(128) stage1_kernel(
    const float* __restrict__ xyz, const int* __restrict__ nidx,
    const float* __restrict__ w1, const float* __restrict__ b1,
    const float* __restrict__ g1, const float* __restrict__ be1,
    const float* __restrict__ fc1w, const float* __restrict__ fc1b,
    const float* __restrict__ ap1w, const float* __restrict__ ap1b,
    const float* __restrict__ ap1g, const float* __restrict__ ap1be)
{
    __shared__ __align__(16) float sh_fxyz[4][KK][12];
    __shared__ __align__(16) float sh_xcat[4][KK][DD];
    __shared__ __align__(16) float sh_agg[4][DD];
    __shared__ int sh_idx[4][KK];

    const int warp = threadIdx.x >> 5;
    const int lane = threadIdx.x & 31;
    const int cm16 = lane & 15;
    const float inv_bn = rsqrtf(1.0f + BN_EPS);

    // conv1 weights for channel cm16, BN folded
    float w1r[10], b1f;
    {
        float s = g1[cm16] * inv_bn;
        #pragma unroll
        for (int i = 0; i < 10; i++) w1r[i] = w1[cm16 * 10 + i] * s;
        b1f = b1[cm16] * s + be1[cm16];
    }
    // fc1 row (lane = channel 0..31)
    float fcr[DD], fcb;
    #pragma unroll
    for (int i = 0; i < DD; i++) fcr[i] = fc1w[lane * DD + i];
    fcb = fc1b[lane];
    // att-pool mlp row (output channel cm16), BN folded
    float apr[DD], apb;
    {
        float s = ap1g[cm16] * inv_bn;
        #pragma unroll
        for (int i = 0; i < DD; i++) apr[i] = ap1w[cm16 * DD + i] * s;
        apb = ap1b[cm16] * s + ap1be[cm16];
    }

    const int b  = blockIdx.x / (NN / 32);
    const int n0 = (blockIdx.x % (NN / 32)) * 32;

    for (int t = 0; t < 8; t++) {
        const int n = n0 + t * 4 + warp;
        const int pn = b * NN + n;

        // -------- geometry: lane j (<16) handles neighbor j --------
        if (lane < KK) {
            int j = lane;
            int idx = nidx[pn * KK + j];
            sh_idx[warp][j] = idx;
            float cx = xyz[pn * 3 + 0], cy = xyz[pn * 3 + 1], cz = xyz[pn * 3 + 2];
            const float* np_ = xyz + (b * NN + idx) * 3;
            float nx = np_[0], ny = np_[1], nz = np_[2];
            float rx = cx - nx, ry = cy - ny, rz = cz - nz;
            float dis = sqrtf(rx * rx + ry * ry + rz * rz);
            float4* row = (float4*)&sh_fxyz[warp][j][0];
            row[0] = make_float4(dis, rx, ry, rz);
            row[1] = make_float4(cx, cy, cz, nx);
            ((float2*)&sh_fxyz[warp][j][8])[0] = make_float2(ny, nz);
        }
        __syncwarp();

        // -------- gather f_nb: lane -> (j = lane/2, half = lane&1) --------
        {
            int j = lane >> 1, h = lane & 1;
            int idx = sh_idx[warp][j];
            const float4* src = (const float4*)(g_feat_t + (b * NN + idx) * HH + h * 8);
            float4 v0 = src[0], v1 = src[1];
            float4* dst = (float4*)&sh_xcat[warp][j][h * 8];
            dst[0] = v0; dst[1] = v1;
        }

        // -------- conv1 (10->16) + BN + LReLU : lane c=cm16, jb split --------
        {
            int jb = (lane >> 4) * 8;
            #pragma unroll
            for (int jj = 0; jj < 8; jj++) {
                int j = jb + jj;
                const float4* xr = (const float4*)&sh_fxyz[warp][j][0];
                float4 a = xr[0], bq = xr[1];
                float2 cq = ((const float2*)&sh_fxyz[warp][j][8])[0];
                float acc = b1f;
                acc += a.x * w1r[0] + a.y * w1r[1] + a.z * w1r[2] + a.w * w1r[3];
                acc += bq.x * w1r[4] + bq.y * w1r[5] + bq.z * w1r[6] + bq.w * w1r[7];
                acc += cq.x * w1r[8] + cq.y * w1r[9];
                sh_xcat[warp][j][HH + cm16] = lrelu(acc);
            }
        }
        __syncwarp();

        // -------- fc1 scores + softmax over k + weighted sum --------
        float sc[KK];
        #pragma unroll
        for (int j = 0; j < KK; j++) {
            const float4* xr = (const float4*)&sh_xcat[warp][j][0];
            float a0 = fcb, a1 = 0.0f;
            #pragma unroll
            for (int q = 0; q < 4; q++) {
                float4 v = xr[q];
                a0 += v.x * fcr[4 * q + 0] + v.y * fcr[4 * q + 1]
                    + v.z * fcr[4 * q + 2] + v.w * fcr[4 * q + 3];
            }
            #pragma unroll
            for (int q = 4; q < 8; q++) {
                float4 v = xr[q];
                a1 += v.x * fcr[4 * q + 0] + v.y * fcr[4 * q + 1]
                    + v.z * fcr[4 * q + 2] + v.w * fcr[4 * q + 3];
            }
            sc[j] = a0 + a1;
        }
        float ssum = 0.0f;
        #pragma unroll
        for (int j = 0; j < KK; j++) { sc[j] = __expf(sc[j]); ssum += sc[j]; }
        float inv = 1.0f / ssum;
        float agg = 0.0f;
        #pragma unroll
        for (int j = 0; j < KK; j++)
            agg += sh_xcat[warp][j][lane] * (sc[j] * inv);
        sh_agg[warp][lane] = agg;
        __syncwarp();

        // -------- mlp (32->16) + BN + LReLU, write f_agg1 --------
        if (lane < HH) {
            const float4* ag = (const float4*)&sh_agg[warp][0];
            float y0 = apb, y1 = 0.0f;
            #pragma unroll
            for (int q = 0; q < 4; q++) {
                float4 v = ag[q];
                y0 += v.x * apr[4 * q + 0] + v.y * apr[4 * q + 1]
                    + v.z * apr[4 * q + 2] + v.w * apr[4 * q + 3];
            }
            #pragma unroll
            for (int q = 4; q < 8; q++) {
                float4 v = ag[q];
                y1 += v.x * apr[4 * q + 0] + v.y * apr[4 * q + 1]
                    + v.z * apr[4 * q + 2] + v.w * apr[4 * q + 3];
            }
            g_agg1[pn * HH + lane] = lrelu(y0 + y1);
        }
        __syncwarp();
    }
}

// ---------------------------------------------------------------------------
// Stage 2: recompute f_xyz1, conv2, gather(f_agg1), att_pool_2 -> output
// Output layout [B, 32, N, 1]; staged in shared for coalesced stores.
// ---------------------------------------------------------------------------
__global__ void __launch_bounds__(128) stage2_kernel(
    const float* __restrict__ xyz, const int* __restrict__ nidx,
    const float* __restrict__ w1, const float* __restrict__ b1,
    const float* __restrict__ g1, const float* __restrict__ be1,
    const float* __restrict__ w2, const float* __restrict__ b2,
    const float* __restrict__ g2, const float* __restrict__ be2,
    const float* __restrict__ fc2w, const float* __restrict__ fc2b,
    const float* __restrict__ ap2w, const float* __restrict__ ap2b,
    const float* __restrict__ ap2g, const float* __restrict__ ap2be,
    float* __restrict__ out)
{
    __shared__ __align__(16) float sh_fxyz[4][KK][12];
    __shared__ __align__(16) float sh_fx1[4][KK][HH];
    __shared__ __align__(16) float sh_xcat[4][KK][DD];
    __shared__ __align__(16) float sh_agg[4][DD];
    __shared__ int sh_idx[4][KK];
    __shared__ float sh_out[DD][33];  // [channel][local point], padded

    const int warp = threadIdx.x >> 5;
    const int lane = threadIdx.x & 31;
    const int cm16 = lane & 15;
    const float inv_bn = rsqrtf(1.0f + BN_EPS);

    float w1r[10], b1f;
    {
        float s = g1[cm16] * inv_bn;
        #pragma unroll
        for (int i = 0; i < 10; i++) w1r[i] = w1[cm16 * 10 + i] * s;
        b1f = b1[cm16] * s + be1[cm16];
    }
    float w2r[HH], b2f;
    {
        float s = g2[cm16] * inv_bn;
        #pragma unroll
        for (int i = 0; i < HH; i++) w2r[i] = w2[cm16 * HH + i] * s;
        b2f = b2[cm16] * s + be2[cm16];
    }
    float fcr[DD], fcb;
    #pragma unroll
    for (int i = 0; i < DD; i++) fcr[i] = fc2w[lane * DD + i];
    fcb = fc2b[lane];
    float apr[DD], apb;
    {
        float s = ap2g[lane] * inv_bn;
        #pragma unroll
        for (int i = 0; i < DD; i++) apr[i] = ap2w[lane * DD + i] * s;
        apb = ap2b[lane] * s + ap2be[lane];
    }

    const int b  = blockIdx.x / (NN / 32);
    const int n0 = (blockIdx.x % (NN / 32)) * 32;

    for (int t = 0; t < 8; t++) {
        const int ln = t * 4 + warp;       // local point in [0,32)
        const int n = n0 + ln;
        const int pn = b * NN + n;

        if (lane < KK) {
            int j = lane;
            int idx = nidx[pn * KK + j];
            sh_idx[warp][j] = idx;
            float cx = xyz[pn * 3 + 0], cy = xyz[pn * 3 + 1], cz = xyz[pn * 3 + 2];
            const float* np_ = xyz + (b * NN + idx) * 3;
            float nx = np_[0], ny = np_[1], nz = np_[2];
            float rx = cx - nx, ry = cy - ny, rz = cz - nz;
            float dis = sqrtf(rx * rx + ry * ry + rz * rz);
            float4* row = (float4*)&sh_fxyz[warp][j][0];
            row[0] = make_float4(dis, rx, ry, rz);
            row[1] = make_float4(cx, cy, cz, nx);
            ((float2*)&sh_fxyz[warp][j][8])[0] = make_float2(ny, nz);
        }
        __syncwarp();

        // gather f_nb2 from g_agg1
        {
            int j = lane >> 1, h = lane & 1;
            int idx = sh_idx[warp][j];
            const float4* src = (const float4*)(g_agg1 + (b * NN + idx) * HH + h * 8);
            float4 v0 = src[0], v1 = src[1];
            float4* dst = (float4*)&sh_xcat[warp][j][h * 8];
            dst[0] = v0; dst[1] = v1;
        }

        // conv1 recompute -> sh_fx1
        {
            int jb = (lane >> 4) * 8;
            #pragma unroll
            for (int jj = 0; jj < 8; jj++) {
                int j = jb + jj;
                const float4* xr = (const float4*)&sh_fxyz[warp][j][0];
                float4 a = xr[0], bq = xr[1];
                float2 cq = ((const float2*)&sh_fxyz[warp][j][8])[0];
                float acc = b1f;
                acc += a.x * w1r[0] + a.y * w1r[1] + a.z * w1r[2] + a.w * w1r[3];
                acc += bq.x * w1r[4] + bq.y * w1r[5] + bq.z * w1r[6] + bq.w * w1r[7];
                acc += cq.x * w1r[8] + cq.y * w1r[9];
                sh_fx1[warp][j][cm16] = lrelu(acc);
            }
        }
        __syncwarp();

        // conv2 (16->16) + BN + LReLU -> sh_xcat[:,16:]
        {
            int jb = (lane >> 4) * 8;
            #pragma unroll
            for (int jj = 0; jj < 8; jj++) {
                int j = jb + jj;
                const float4* xr = (const float4*)&sh_fx1[warp][j][0];
                float acc0 = b2f, acc1 = 0.0f;
                #pragma unroll
                for (int q = 0; q < 2; q++) {
                    float4 v = xr[q];
                    acc0 += v.x * w2r[4 * q + 0] + v.y * w2r[4 * q + 1]
                          + v.z * w2r[4 * q + 2] + v.w * w2r[4 * q + 3];
                }
                #pragma unroll
                for (int q = 2; q < 4; q++) {
                    float4 v = xr[q];
                    acc1 += v.x * w2r[4 * q + 0] + v.y * w2r[4 * q + 1]
                          + v.z * w2r[4 * q + 2] + v.w * w2r[4 * q + 3];
                }
                sh_xcat[warp][j][HH + cm16] = lrelu(acc0 + acc1);
            }
        }
        __syncwarp();

        // fc2 + softmax + weighted sum
        float sc[KK];
        #pragma unroll
        for (int j = 0; j < KK; j++) {
            const float4* xr = (const float4*)&sh_xcat[warp][j][0];
            float a0 = fcb, a1 = 0.0f;
            #pragma unroll
            for (int q = 0; q < 4; q++) {
                float4 v = xr[q];
                a0 += v.x * fcr[4 * q + 0] + v.y * fcr[4 * q + 1]
                    + v.z * fcr[4 * q + 2] + v.w * fcr[4 * q + 3];
            }
            #pragma unroll
            for (int q = 4; q < 8; q++) {
                float4 v = xr[q];
                a1 += v.x * fcr[4 * q + 0] + v.y * fcr[4 * q + 1]
                    + v.z * fcr[4 * q + 2] + v.w * fcr[4 * q + 3];
            }
            sc[j] = a0 + a1;
        }
        float ssum = 0.0f;
        #pragma unroll
        for (int j = 0; j < KK; j++) { sc[j] = __expf(sc[j]); ssum += sc[j]; }
        float inv = 1.0f / ssum;
        float agg = 0.0f;
        #pragma unroll
        for (int j = 0; j < KK; j++)
            agg += sh_xcat[warp][j][lane] * (sc[j] * inv);
        sh_agg[warp][lane] = agg;
        __syncwarp();

        // mlp2 (32->32) + BN + LReLU -> staged output
        {
            const float4* ag = (const float4*)&sh_agg[warp][0];
            float y0 = apb, y1 = 0.0f;
            #pragma unroll
            for (int q = 0; q < 4; q++) {
                float4 v = ag[q];
                y0 += v.x * apr[4 * q + 0] + v.y * apr[4 * q + 1]
                    + v.z * apr[4 * q + 2] + v.w * apr[4 * q + 3];
            }
            #pragma unroll
            for (int q = 4; q < 8; q++) {
                float4 v = ag[q];
                y1 += v.x * apr[4 * q + 0] + v.y * apr[4 * q + 1]
                    + v.z * apr[4 * q + 2] + v.w * apr[4 * q + 3];
            }
            sh_out[lane][ln] = lrelu(y0 + y1);
        }
        __syncwarp();
    }

    __syncthreads();
    // cooperative coalesced store: out[(b*32 + c)*N + n0 + ln]
    for (int e = threadIdx.x; e < DD * 32; e += 128) {
        int c = e >> 5, ln = e & 31;
        out[(b * DD + c) * NN + n0 + ln] = sh_out[c][ln];
    }
}

// ---------------------------------------------------------------------------
extern "C" void kernel_launch(void* const* d_in, const int* in_sizes, int n_in,
                              void* d_out, int out_size) {
    const float* xyz     = (const float*)d_in[0];
    const float* feature = (const float*)d_in[1];
    const int*   nidx    = (const int*)  d_in[2];
    const float* w1   = (const float*)d_in[3];
    const float* b1   = (const float*)d_in[4];
    const float* g1   = (const float*)d_in[5];
    const float* be1  = (const float*)d_in[6];
    const float* fc1w = (const float*)d_in[7];
    const float* fc1b = (const float*)d_in[8];
    const float* ap1w = (const float*)d_in[9];
    const float* ap1b = (const float*)d_in[10];
    const float* ap1g = (const float*)d_in[11];
    const float* ap1be= (const float*)d_in[12];
    const float* w2   = (const float*)d_in[13];
    const float* b2   = (const float*)d_in[14];
    const float* g2   = (const float*)d_in[15];
    const float* be2  = (const float*)d_in[16];
    const float* fc2w = (const float*)d_in[17];
    const float* fc2b = (const float*)d_in[18];
    const float* ap2w = (const float*)d_in[19];
    const float* ap2b = (const float*)d_in[20];
    const float* ap2g = (const float*)d_in[21];
    const float* ap2be= (const float*)d_in[22];
    float* out = (float*)d_out;

    transpose_feat_kernel<<<dim3(NN / 64, BB), 256>>>(feature);
    stage1_kernel<<<BB * NN / 32, 128>>>(xyz, nidx, w1, b1, g1, be1,
                                         fc1w, fc1b, ap1w, ap1b, ap1g, ap1be);
    stage2_kernel<<<BB * NN / 32, 128>>>(xyz, nidx, w1, b1, g1, be1,
                                         w2, b2, g2, be2, fc2w, fc2b,
                                         ap2w, ap2b, ap2g, ap2be, out);
}